// round 10
// baseline (speedup 1.0000x reference)
#include <cuda_runtime.h>
#include <math.h>

// VIN: B=128 images 64x64, L_I=2, L_H=150 (collapsed analytically), L_Q=10, K=50.
// Grid = 4 CTAs x 1024 threads; one WARP per image (32 images/CTA).
// Fast path (w==0, verified at runtime): VI scan is the identity and v never
// reaches the output -> per-image answer needs only a 5x5 X patch. ONE block
// barrier total; W_eff reduce done redundantly per warp after it.
// Slow path (w!=0): full VI per image on __device__ global scratch.

#define NT    1024
#define GRID  4
#define PADW  68
#define BUF   4488        // 66*68

__device__ float g_scr[GRID][3*BUF];   // slow-path scratch (never hot)

__global__ __launch_bounds__(NT, 1)
void vin_kernel(const float* __restrict__ X,
                const float* __restrict__ h_w,
                const float* __restrict__ h_b,
                const float* __restrict__ r_w,
                const float* __restrict__ q_w,
                const float* __restrict__ w,
                const float* __restrict__ fc_w,
                const void*  S1v, const void* S2v,
                const void*  kv,
                float* __restrict__ out)
{
    __shared__ float qw_s[90];            // q_w
    __shared__ float fc_s[80];            // fc_w
    __shared__ float ws[90];              // w (slow path)
    __shared__ float partial_s[152];      // W_eff partial sums (19 outs x 8 chunks)
    __shared__ float weff_sh[32][20];     // per-warp W_eff copy (+bias), padded
    __shared__ float xs_s[32][50];        // per-warp 2ch x 5x5 X patch
    __shared__ float rp_sh[32][9];        // per-warp 3x3 r patch
    __shared__ float qv_sh[32][10];       // per-warp q at gather pixel
    __shared__ int   s64_sm, kval_s;

    const int t    = threadIdx.x;
    const int warp = t >> 5;
    const int lane = t & 31;
    const int b    = blockIdx.x * 32 + warp;    // this warp's image

    // ---------- Warp-local loads: the dependent chain issues immediately ----------
    float wv0 = 0.f, wv1 = 0.f, wv2 = 0.f;
    {
        int i0 = lane * 3;
        if (i0     < 90) wv0 = w[i0];
        if (i0 + 1 < 90) wv1 = w[i0 + 1];
        if (i0 + 2 < 90) wv2 = w[i0 + 2];
    }
    // int64-vs-int32 layout probe: int64 LE => all high words zero (vals < 64).
    int hi = ((const int*)S1v)[2*lane + 1] | ((const int*)S1v)[2*(lane + 32) + 1];
    // S candidates for this warp's image, one per lane 0..3.
    int scand = 0;
    if      (lane == 0) scand = ((const int*)S1v)[b];
    else if (lane == 1) scand = (int)((const long long*)S1v)[b];
    else if (lane == 2) scand = ((const int*)S2v)[b];
    else if (lane == 3) scand = (int)((const long long*)S2v)[b];

    unsigned wb = __ballot_sync(0xFFFFFFFFu, (wv0 != 0.f) || (wv1 != 0.f) || (wv2 != 0.f));
    unsigned pb = __ballot_sync(0xFFFFFFFFu, hi != 0);
    const int wnz = (wb != 0u);
    const int s64 = (pb == 0u);
    const int si  = __shfl_sync(0xFFFFFFFFu, scand, s64 ? 1 : 0);
    const int sj  = __shfl_sync(0xFFFFFFFFu, scand, s64 ? 3 : 2);

    // X patch loads (trip 2 of the dependent chain) — warp-local, pre-barrier.
    #pragma unroll
    for (int q2 = 0; q2 < 2; q2++) {
        int p = 2*lane + q2;
        if (p < 50) {
            int c = p / 25, rr = (p % 25) / 5, cc = p % 5;
            int ii = si - 2 + rr, jj = sj - 2 + cc;
            xs_s[warp][p] = (ii >= 0 && ii < 64 && jj >= 0 && jj < 64)
                          ? X[(size_t)b*8192 + c*4096 + ii*64 + jj] : 0.0f;
        }
    }

    // ---------- Block-wide small loads + W_eff partials (pre-barrier) ----------
    if (t >= 512 && t < 602) qw_s[t - 512] = q_w[t - 512];
    if (t >= 640 && t < 720) fc_s[t - 640] = fc_w[t - 640];
    if (t == 736) kval_s = kv ? ((const int*)kv)[0] : 50;   // LE low word
    if (warp == 0) {               // stash w + s64 flag for slow path
        int i0 = lane * 3;
        if (i0     < 90) ws[i0]     = wv0;
        if (i0 + 1 < 90) ws[i0 + 1] = wv1;
        if (i0 + 2 < 90) ws[i0 + 2] = wv2;
        if (lane == 0) s64_sm = s64;
    }
    if (t < 152) {  // 19 outputs x 8 chunks over 150 hidden channels
        int o = t >> 3, c = t & 7;
        int h0 = c * 19, h1 = (h0 + 19 < 150) ? h0 + 19 : 150;
        float acc = 0.0f;
        if (o < 18) { for (int h = h0; h < h1; h++) acc += r_w[h] * h_w[h*18 + o]; }
        else        { for (int h = h0; h < h1; h++) acc += r_w[h] * h_b[h]; }
        partial_s[t] = acc;
    }
    __syncthreads();     // the ONLY block barrier on the fast path

    // Per-warp redundant W_eff reduce (replaces a second block barrier).
    if (lane < 19) {
        float a = 0.0f;
        #pragma unroll
        for (int c = 0; c < 8; c++) a += partial_s[lane*8 + c];
        weff_sh[warp][lane] = a;
    }
    __syncwarp();

    if (!wnz) {
        // ================= FAST PATH (w == 0): fully warp-local =================
        const float* weff = weff_sh[warp];
        if (lane < 9) {
            int dy = lane / 3, dx = lane % 3;
            int ii = si - 1 + dy, jj = sj - 1 + dx;
            float vv = 0.0f;                          // SAME-pad zero for q conv
            if (ii >= 0 && ii < 64 && jj >= 0 && jj < 64) {
                float acc = weff[18];
                #pragma unroll
                for (int c = 0; c < 2; c++)
                    #pragma unroll
                    for (int ky = 0; ky < 3; ky++)
                        #pragma unroll
                        for (int kx = 0; kx < 3; kx++)
                            acc += weff[c*9 + ky*3 + kx]
                                 * xs_s[warp][c*25 + (dy+ky)*5 + (dx+kx)];
                vv = acc;
            }
            rp_sh[warp][lane] = vv;
        }
        __syncwarp();
        if (lane < 10) {
            float acc = 0.0f;
            #pragma unroll
            for (int m = 0; m < 9; m++) acc += qw_s[lane*9 + m] * rp_sh[warp][m];
            qv_sh[warp][lane] = acc;
        }
        __syncwarp();
        if (lane < 8) {
            float lg = 0.0f;
            #pragma unroll
            for (int a = 0; a < 10; a++) lg += qv_sh[warp][a] * fc_s[lane*10 + a];
            float m = lg;
            #pragma unroll
            for (int d = 4; d >= 1; d >>= 1)
                m = fmaxf(m, __shfl_xor_sync(0xFFu, m, d));
            float ex = __expf(lg - m);
            float den = ex;
            #pragma unroll
            for (int d = 4; d >= 1; d >>= 1)
                den += __shfl_xor_sync(0xFFu, den, d);
            float inv = 1.0f / den;
            out[b*8 + lane]         = lg;             // logits block
            out[128*8 + b*8 + lane] = ex * inv;       // probs block
        }
        return;
    }

    // ========== SLOW PATH (w != 0): full VI per image, global scratch ==========
    const float* weff0 = weff_sh[0];       // warp 0's copy; visible after barriers
    float* r_s = g_scr[blockIdx.x];
    float* va  = r_s + BUF;
    float* vb  = r_s + 2*BUF;

    for (int img = 0; img < 32; img++) {
        const int b2 = blockIdx.x * 32 + img;
        for (int idx = t; idx < 3*BUF; idx += NT) r_s[idx] = 0.0f;
        __syncthreads();
        const int K = kval_s;

        // r = conv3x3(X, W_eff) + b_eff (SAME)
        {
            const float beff = weff0[18];
            const float* X0 = X + (size_t)b2 * 8192;
            #pragma unroll 1
            for (int s = 0; s < 4; s++) {
                int p = s*NT + t;
                int i = p >> 6, j = p & 63;
                float acc = beff;
                #pragma unroll
                for (int c = 0; c < 2; c++) {
                    const float* Xc = X0 + c*4096;
                    #pragma unroll
                    for (int dy = 0; dy < 3; dy++) {
                        int ii = i + dy - 1;
                        #pragma unroll
                        for (int dx = 0; dx < 3; dx++) {
                            int jj = j + dx - 1;
                            if (ii >= 0 && ii < 64 && jj >= 0 && jj < 64)
                                acc += weff0[c*9 + dy*3 + dx] * Xc[ii*64 + jj];
                        }
                    }
                }
                r_s[(i+1)*PADW + (j+1)] = acc;
            }
        }
        __syncthreads();

        // v0 = max_a conv3x3(r, q_w[a])
        #pragma unroll 1
        for (int s = 0; s < 4; s++) {
            int p = s*NT + t;
            int i = p >> 6, j = p & 63;
            float n[9];
            #pragma unroll
            for (int dy = 0; dy < 3; dy++)
                #pragma unroll
                for (int dx = 0; dx < 3; dx++)
                    n[dy*3 + dx] = r_s[(i+dy)*PADW + (j+dx)];
            float vmax = -3.402823466e38f;
            #pragma unroll
            for (int a = 0; a < 10; a++) {
                float acc = 0.0f;
                #pragma unroll
                for (int m = 0; m < 9; m++) acc += qw_s[a*9 + m] * n[m];
                vmax = fmaxf(vmax, acc);
            }
            va[(i+1)*PADW + (j+1)] = vmax;
        }
        __syncthreads();

        // v <- max_a ( conv3x3(r, q_w[a]) + conv3x3(v, w[a]) )
        float* vcur = va;
        float* vnxt = vb;
        for (int it = 0; it < K - 1; it++) {
            #pragma unroll 1
            for (int s = 0; s < 4; s++) {
                int p = s*NT + t;
                int i = p >> 6, j = p & 63;
                float rn[9], vn[9];
                #pragma unroll
                for (int dy = 0; dy < 3; dy++)
                    #pragma unroll
                    for (int dx = 0; dx < 3; dx++) {
                        rn[dy*3 + dx] = r_s [(i+dy)*PADW + (j+dx)];
                        vn[dy*3 + dx] = vcur[(i+dy)*PADW + (j+dx)];
                    }
                float vmax = -3.402823466e38f;
                #pragma unroll
                for (int a = 0; a < 10; a++) {
                    float acc = 0.0f;
                    #pragma unroll
                    for (int m = 0; m < 9; m++)
                        acc += qw_s[a*9 + m]*rn[m] + ws[a*9 + m]*vn[m];
                    vmax = fmaxf(vmax, acc);
                }
                vnxt[(i+1)*PADW + (j+1)] = vmax;
            }
            float* tmp = vcur; vcur = vnxt; vnxt = tmp;
            __syncthreads();
        }

        if (t == 0) {
            int si2, sj2;
            if (s64_sm) {
                si2 = (int)((const long long*)S1v)[b2];
                sj2 = (int)((const long long*)S2v)[b2];
            } else {
                si2 = ((const int*)S1v)[b2];
                sj2 = ((const int*)S2v)[b2];
            }
            float qout[10];
            #pragma unroll
            for (int a = 0; a < 10; a++) {
                float acc = 0.0f;
                #pragma unroll
                for (int dy = 0; dy < 3; dy++)
                    #pragma unroll
                    for (int dx = 0; dx < 3; dx++)
                        acc += qw_s[a*9 + dy*3 + dx] * r_s [(si2+dy)*PADW + (sj2+dx)]
                             + ws  [a*9 + dy*3 + dx] * vcur[(si2+dy)*PADW + (sj2+dx)];
                qout[a] = acc;
            }
            float logits[8], lmax = -3.402823466e38f;
            #pragma unroll
            for (int j = 0; j < 8; j++) {
                float acc = 0.0f;
                #pragma unroll
                for (int a = 0; a < 10; a++) acc += qout[a] * fc_s[j*10 + a];
                logits[j] = acc;
                lmax = fmaxf(lmax, acc);
            }
            float ex[8], den = 0.0f;
            #pragma unroll
            for (int j = 0; j < 8; j++) { ex[j] = __expf(logits[j] - lmax); den += ex[j]; }
            float inv = 1.0f / den;
            #pragma unroll
            for (int j = 0; j < 8; j++) {
                out[b2*8 + j]         = logits[j];
                out[128*8 + b2*8 + j] = ex[j] * inv;
            }
        }
        __syncthreads();   // scratch reuse for next image
    }
}

extern "C" void kernel_launch(void* const* d_in, const int* in_sizes, int n_in,
                              void* d_out, int out_size)
{
    (void)in_sizes; (void)out_size;
    const float* X    = (const float*)d_in[0];
    const float* h_w  = (const float*)d_in[1];
    const float* h_b  = (const float*)d_in[2];
    const float* r_w  = (const float*)d_in[3];
    const float* q_w  = (const float*)d_in[4];
    const float* w    = (const float*)d_in[5];
    const float* fc_w = (const float*)d_in[6];
    const void*  S1   = d_in[7];
    const void*  S2   = d_in[8];
    // d_in[9], d_in[10] = O1, O2: unused by the reference computation
    const void*  kv   = (n_in > 11) ? d_in[11] : nullptr;

    vin_kernel<<<GRID, NT>>>(X, h_w, h_b, r_w, q_w, w, fc_w, S1, S2, kv,
                             (float*)d_out);
}

// round 12
// speedup vs baseline: 1.8073x; 1.8073x over previous
#include <cuda_runtime.h>
#include <math.h>

// VIN: B=128 images 64x64, L_I=2, L_H=150 (collapsed analytically), L_Q=10, K=50.
// Grid = 16 CTAs x 256 threads; one WARP per image (8 images/CTA). Best-known
// launch shape (R8) + single block barrier (R9's good half).
// Fast path (w==0, verified at runtime): VI scan is the identity and v never
// reaches the output -> per-image answer needs only a 5x5 X patch.
// Slow path (w!=0): full VI per image on __device__ global scratch.

#define NT    256
#define GRID  16
#define PADW  68
#define BUF   4488        // 66*68

__device__ float g_scr[GRID][3*BUF];   // slow-path scratch (never hot)

__global__ __launch_bounds__(NT, 1)
void vin_kernel(const float* __restrict__ X,
                const float* __restrict__ h_w,
                const float* __restrict__ h_b,
                const float* __restrict__ r_w,
                const float* __restrict__ q_w,
                const float* __restrict__ w,
                const float* __restrict__ fc_w,
                const void*  S1v, const void* S2v,
                const void*  kv,
                float* __restrict__ out)
{
    __shared__ float qw_s[90];            // q_w
    __shared__ float fc_s[80];            // fc_w
    __shared__ float ws[90];              // w (slow path)
    __shared__ float partial_s[152];      // W_eff partials (19 outs x 8 chunks)
    __shared__ float weff_sh[8][20];      // per-warp W_eff copy (+bias)
    __shared__ float xs_s[8][50];         // per-warp 2ch x 5x5 X patch
    __shared__ float rp_sh[8][9];         // per-warp 3x3 r patch
    __shared__ float qv_sh[8][10];        // per-warp q at gather pixel
    __shared__ int   s64_sm, kval_s;

    const int t    = threadIdx.x;
    const int warp = t >> 5;
    const int lane = t & 31;
    const int b    = blockIdx.x * 8 + warp;     // this warp's image

    // ---------- Warp-local loads: the dependent chain issues immediately ----------
    float wv0 = 0.f, wv1 = 0.f, wv2 = 0.f;
    {
        int i0 = lane * 3;
        if (i0     < 90) wv0 = w[i0];
        if (i0 + 1 < 90) wv1 = w[i0 + 1];
        if (i0 + 2 < 90) wv2 = w[i0 + 2];
    }
    // int64-vs-int32 layout probe: int64 LE => all high words zero (vals < 64).
    int hi = ((const int*)S1v)[2*lane + 1] | ((const int*)S1v)[2*(lane + 32) + 1];
    // S candidates for this warp's image, one per lane 0..3.
    int scand = 0;
    if      (lane == 0) scand = ((const int*)S1v)[b];
    else if (lane == 1) scand = (int)((const long long*)S1v)[b];
    else if (lane == 2) scand = ((const int*)S2v)[b];
    else if (lane == 3) scand = (int)((const long long*)S2v)[b];

    unsigned wb = __ballot_sync(0xFFFFFFFFu, (wv0 != 0.f) || (wv1 != 0.f) || (wv2 != 0.f));
    unsigned pb = __ballot_sync(0xFFFFFFFFu, hi != 0);
    const int wnz = (wb != 0u);
    const int s64 = (pb == 0u);
    const int si  = __shfl_sync(0xFFFFFFFFu, scand, s64 ? 1 : 0);
    const int sj  = __shfl_sync(0xFFFFFFFFu, scand, s64 ? 3 : 2);

    // X patch loads (trip 2 of the dependent chain) — warp-local, pre-barrier.
    #pragma unroll
    for (int q2 = 0; q2 < 2; q2++) {
        int p = 2*lane + q2;
        if (p < 50) {
            int c = p / 25, rr = (p % 25) / 5, cc = p % 5;
            int ii = si - 2 + rr, jj = sj - 2 + cc;
            xs_s[warp][p] = (ii >= 0 && ii < 64 && jj >= 0 && jj < 64)
                          ? X[(size_t)b*8192 + c*4096 + ii*64 + jj] : 0.0f;
        }
    }

    // ---------- Block-wide small loads + W_eff partials (pre-barrier) ----------
    if (t >= 160 && t < 250) qw_s[t - 160] = q_w[t - 160];
    if (t < 80) fc_s[t] = fc_w[t];
    if (t == 255) kval_s = kv ? ((const int*)kv)[0] : 50;   // LE low word
    if (warp == 0) {               // stash w + s64 flag for slow path
        int i0 = lane * 3;
        if (i0     < 90) ws[i0]     = wv0;
        if (i0 + 1 < 90) ws[i0 + 1] = wv1;
        if (i0 + 2 < 90) ws[i0 + 2] = wv2;
        if (lane == 0) s64_sm = s64;
    }
    if (t < 152) {  // 19 outputs x 8 chunks over 150 hidden channels
        int o = t >> 3, c = t & 7;
        int h0 = c * 19, h1 = (h0 + 19 < 150) ? h0 + 19 : 150;
        float acc = 0.0f;
        if (o < 18) { for (int h = h0; h < h1; h++) acc += r_w[h] * h_w[h*18 + o]; }
        else        { for (int h = h0; h < h1; h++) acc += r_w[h] * h_b[h]; }
        partial_s[t] = acc;
    }
    __syncthreads();     // the ONLY block barrier on the fast path

    // Per-warp redundant W_eff reduce (replaces a second block barrier).
    if (lane < 19) {
        float a = 0.0f;
        #pragma unroll
        for (int c = 0; c < 8; c++) a += partial_s[lane*8 + c];
        weff_sh[warp][lane] = a;
    }
    __syncwarp();

    if (!wnz) {
        // ================= FAST PATH (w == 0): fully warp-local =================
        const float* weff = weff_sh[warp];
        if (lane < 9) {
            int dy = lane / 3, dx = lane % 3;
            int ii = si - 1 + dy, jj = sj - 1 + dx;
            float vv = 0.0f;                          // SAME-pad zero for q conv
            if (ii >= 0 && ii < 64 && jj >= 0 && jj < 64) {
                float acc = weff[18];
                #pragma unroll
                for (int c = 0; c < 2; c++)
                    #pragma unroll
                    for (int ky = 0; ky < 3; ky++)
                        #pragma unroll
                        for (int kx = 0; kx < 3; kx++)
                            acc += weff[c*9 + ky*3 + kx]
                                 * xs_s[warp][c*25 + (dy+ky)*5 + (dx+kx)];
                vv = acc;
            }
            rp_sh[warp][lane] = vv;
        }
        __syncwarp();
        if (lane < 10) {
            float acc = 0.0f;
            #pragma unroll
            for (int m = 0; m < 9; m++) acc += qw_s[lane*9 + m] * rp_sh[warp][m];
            qv_sh[warp][lane] = acc;
        }
        __syncwarp();
        if (lane < 8) {
            float lg = 0.0f;
            #pragma unroll
            for (int a = 0; a < 10; a++) lg += qv_sh[warp][a] * fc_s[lane*10 + a];
            float m = lg;
            #pragma unroll
            for (int d = 4; d >= 1; d >>= 1)
                m = fmaxf(m, __shfl_xor_sync(0xFFu, m, d));
            float ex = __expf(lg - m);
            float den = ex;
            #pragma unroll
            for (int d = 4; d >= 1; d >>= 1)
                den += __shfl_xor_sync(0xFFu, den, d);
            float inv = 1.0f / den;
            out[b*8 + lane]         = lg;             // logits block
            out[128*8 + b*8 + lane] = ex * inv;       // probs block
        }
        return;
    }

    // ========== SLOW PATH (w != 0): full VI per image, global scratch ==========
    float* r_s = g_scr[blockIdx.x];
    float* va  = r_s + BUF;
    float* vb  = r_s + 2*BUF;
    const float* weff0 = weff_sh[0];   // warp 0's copy; ordered by barriers below

    for (int img = 0; img < 8; img++) {
        const int b2 = blockIdx.x * 8 + img;
        for (int idx = t; idx < 3*BUF; idx += NT) r_s[idx] = 0.0f;
        __syncthreads();
        const int K = kval_s;

        // r = conv3x3(X, W_eff) + b_eff (SAME)
        {
            const float beff = weff0[18];
            const float* X0 = X + (size_t)b2 * 8192;
            #pragma unroll 1
            for (int s = 0; s < 16; s++) {
                int p = s*NT + t;
                int i = p >> 6, j = p & 63;
                float acc = beff;
                #pragma unroll
                for (int c = 0; c < 2; c++) {
                    const float* Xc = X0 + c*4096;
                    #pragma unroll
                    for (int dy = 0; dy < 3; dy++) {
                        int ii = i + dy - 1;
                        #pragma unroll
                        for (int dx = 0; dx < 3; dx++) {
                            int jj = j + dx - 1;
                            if (ii >= 0 && ii < 64 && jj >= 0 && jj < 64)
                                acc += weff0[c*9 + dy*3 + dx] * Xc[ii*64 + jj];
                        }
                    }
                }
                r_s[(i+1)*PADW + (j+1)] = acc;
            }
        }
        __syncthreads();

        // v0 = max_a conv3x3(r, q_w[a])
        #pragma unroll 1
        for (int s = 0; s < 16; s++) {
            int p = s*NT + t;
            int i = p >> 6, j = p & 63;
            float n[9];
            #pragma unroll
            for (int dy = 0; dy < 3; dy++)
                #pragma unroll
                for (int dx = 0; dx < 3; dx++)
                    n[dy*3 + dx] = r_s[(i+dy)*PADW + (j+dx)];
            float vmax = -3.402823466e38f;
            #pragma unroll
            for (int a = 0; a < 10; a++) {
                float acc = 0.0f;
                #pragma unroll
                for (int m = 0; m < 9; m++) acc += qw_s[a*9 + m] * n[m];
                vmax = fmaxf(vmax, acc);
            }
            va[(i+1)*PADW + (j+1)] = vmax;
        }
        __syncthreads();

        // v <- max_a ( conv3x3(r, q_w[a]) + conv3x3(v, w[a]) )
        float* vcur = va;
        float* vnxt = vb;
        for (int it = 0; it < K - 1; it++) {
            #pragma unroll 1
            for (int s = 0; s < 16; s++) {
                int p = s*NT + t;
                int i = p >> 6, j = p & 63;
                float rn[9], vn[9];
                #pragma unroll
                for (int dy = 0; dy < 3; dy++)
                    #pragma unroll
                    for (int dx = 0; dx < 3; dx++) {
                        rn[dy*3 + dx] = r_s [(i+dy)*PADW + (j+dx)];
                        vn[dy*3 + dx] = vcur[(i+dy)*PADW + (j+dx)];
                    }
                float vmax = -3.402823466e38f;
                #pragma unroll
                for (int a = 0; a < 10; a++) {
                    float acc = 0.0f;
                    #pragma unroll
                    for (int m = 0; m < 9; m++)
                        acc += qw_s[a*9 + m]*rn[m] + ws[a*9 + m]*vn[m];
                    vmax = fmaxf(vmax, acc);
                }
                vnxt[(i+1)*PADW + (j+1)] = vmax;
            }
            float* tmp = vcur; vcur = vnxt; vnxt = tmp;
            __syncthreads();
        }

        if (t == 0) {
            int si2, sj2;
            if (s64_sm) {
                si2 = (int)((const long long*)S1v)[b2];
                sj2 = (int)((const long long*)S2v)[b2];
            } else {
                si2 = ((const int*)S1v)[b2];
                sj2 = ((const int*)S2v)[b2];
            }
            float qout[10];
            #pragma unroll
            for (int a = 0; a < 10; a++) {
                float acc = 0.0f;
                #pragma unroll
                for (int dy = 0; dy < 3; dy++)
                    #pragma unroll
                    for (int dx = 0; dx < 3; dx++)
                        acc += qw_s[a*9 + dy*3 + dx] * r_s [(si2+dy)*PADW + (sj2+dx)]
                             + ws  [a*9 + dy*3 + dx] * vcur[(si2+dy)*PADW + (sj2+dx)];
                qout[a] = acc;
            }
            float logits[8], lmax = -3.402823466e38f;
            #pragma unroll
            for (int j = 0; j < 8; j++) {
                float acc = 0.0f;
                #pragma unroll
                for (int a = 0; a < 10; a++) acc += qout[a] * fc_s[j*10 + a];
                logits[j] = acc;
                lmax = fmaxf(lmax, acc);
            }
            float ex[8], den = 0.0f;
            #pragma unroll
            for (int j = 0; j < 8; j++) { ex[j] = __expf(logits[j] - lmax); den += ex[j]; }
            float inv = 1.0f / den;
            #pragma unroll
            for (int j = 0; j < 8; j++) {
                out[b2*8 + j]         = logits[j];
                out[128*8 + b2*8 + j] = ex[j] * inv;
            }
        }
        __syncthreads();   // scratch reuse for next image
    }
}

extern "C" void kernel_launch(void* const* d_in, const int* in_sizes, int n_in,
                              void* d_out, int out_size)
{
    (void)in_sizes; (void)out_size;
    const float* X    = (const float*)d_in[0];
    const float* h_w  = (const float*)d_in[1];
    const float* h_b  = (const float*)d_in[2];
    const float* r_w  = (const float*)d_in[3];
    const float* q_w  = (const float*)d_in[4];
    const float* w    = (const float*)d_in[5];
    const float* fc_w = (const float*)d_in[6];
    const void*  S1   = d_in[7];
    const void*  S2   = d_in[8];
    // d_in[9], d_in[10] = O1, O2: unused by the reference computation
    const void*  kv   = (n_in > 11) ? d_in[11] : nullptr;

    vin_kernel<<<GRID, NT>>>(X, h_w, h_b, r_w, q_w, w, fc_w, S1, S2, kv,
                             (float*)d_out);
}